// round 6
// baseline (speedup 1.0000x reference)
#include <cuda_runtime.h>
#include <cuda_fp16.h>
#include <cstdint>

// ---------------- problem dims ----------------
static constexpr int N_ROWS = 8192;    // samples
static constexpr int C_CLS  = 1000;    // classes
static constexpr int D_DIM  = 10000;   // hypervector dim
static constexpr int D_PAD  = 10240;   // padded: 160 * 64 (zeros contribute 0 to dot)
static constexpr int C_PAD  = 1024;    // padded classes (rows >= 1000 are zero)

// ---------------- GEMM tiling (fp16, f16-accum with exact chunked spill) ----
static constexpr int BM = 128;
static constexpr int BN = 128;
static constexpr int BK = 64;               // 64 fp16 = 128B rows
static constexpr int KT = D_PAD / BK;       // 160 K-iterations
static constexpr int SPILL_EVERY = 32;      // 32*64 = 2048 k-elems: exact in fp16
static constexpr int STAGES = 3;

static constexpr int A_BYTES = BM * BK * 2;            // 16384
static constexpr int STAGE_BYTES = (BM + BN) * BK * 2; // 32768
static constexpr int SMEM_TOTAL = STAGES * STAGE_BYTES; // 98304

// ---------------- scratch (device globals; no allocation allowed) ----------
__device__ uint16_t g_A[(size_t)N_ROWS * D_PAD];   // 168 MB fp16
__device__ uint16_t g_B[(size_t)C_PAD  * D_PAD];   // 21 MB fp16
__device__ int g_ssum[N_ROWS];
__device__ int g_csum[C_PAD];

// ---------------- helpers ----------------
__device__ __forceinline__ uint32_t smem_to_u32(const void* p) {
    uint32_t a;
    asm("{ .reg .u64 t; cvta.to.shared.u64 t, %1; cvt.u32.u64 %0, t; }" : "=r"(a) : "l"(p));
    return a;
}

__device__ __forceinline__ void cp_async16(uint32_t smem_addr, const void* gptr) {
    asm volatile("cp.async.cg.shared.global [%0], [%1], 16;"
                 :: "r"(smem_addr), "l"(gptr) : "memory");
}
#define CP_COMMIT() asm volatile("cp.async.commit_group;" ::: "memory")
#define CP_WAIT1()  asm volatile("cp.async.wait_group 1;" ::: "memory")

#define LDSM_X4(r0, r1, r2, r3, addr) \
    asm volatile("ldmatrix.sync.aligned.m8n8.x4.shared.b16 {%0,%1,%2,%3}, [%4];" \
                 : "=r"(r0), "=r"(r1), "=r"(r2), "=r"(r3) : "r"(addr))

// fp16 MMA, fp16 accumulate (D,C packed half2 x2): D += A(16x16)*B(16x8)^T
#define MMA_F16ACC(d, a, b) \
    asm volatile("mma.sync.aligned.m16n8k16.row.col.f16.f16.f16.f16 " \
                 "{%0,%1}, {%2,%3,%4,%5}, {%6,%7}, {%0,%1};" \
                 : "+r"((d)[0]), "+r"((d)[1]) \
                 : "r"((a)[0]), "r"((a)[1]), "r"((a)[2]), "r"((a)[3]), \
                   "r"((b)[0]), "r"((b)[1]))

// pack two {0,1} floats into one u32 holding two fp16 (1.0 = 0x3C00)
__device__ __forceinline__ uint32_t packh2(float lo, float hi) {
    return ((uint32_t)(int)lo * 0x3C00u) | (((uint32_t)(int)hi * 0x3C00u) << 16);
}

// ---------------- conversion: fp32 {0,1} -> fp16, fused integer row-sum ----
__global__ void __launch_bounds__(256) cvt_kernel(const float* __restrict__ src,
                                                  uint16_t* __restrict__ dst,
                                                  int* __restrict__ sums,
                                                  int valid_rows) {
    const int row = blockIdx.x;
    const int tid = threadIdx.x;
    int acc = 0;
    uint4* d4 = reinterpret_cast<uint4*>(dst + (size_t)row * D_PAD);  // 16B = 8 fp16
    if (row < valid_rows) {
        const float4* s4 = reinterpret_cast<const float4*>(src + (size_t)row * D_DIM);
        // D_DIM/8 = 1250 full 8-elem chunks; chunks 1250..1279 are zero padding
        for (int i = tid; i < D_PAD / 8; i += 256) {
            uint4 o;
            if (i < D_DIM / 8) {
                float4 v0 = s4[i * 2 + 0];
                float4 v1 = s4[i * 2 + 1];
                float fs = v0.x + v0.y + v0.z + v0.w + v1.x + v1.y + v1.z + v1.w;
                acc += (int)fs;   // sum of 8 {0,1} values: exact
                o.x = packh2(v0.x, v0.y);
                o.y = packh2(v0.z, v0.w);
                o.z = packh2(v1.x, v1.y);
                o.w = packh2(v1.z, v1.w);
            } else {
                o.x = 0u; o.y = 0u; o.z = 0u; o.w = 0u;
            }
            d4[i] = o;
        }
    } else {
        uint4 z; z.x = 0u; z.y = 0u; z.z = 0u; z.w = 0u;
        for (int i = tid; i < D_PAD / 8; i += 256) d4[i] = z;
    }
    // block reduce (int)
    __shared__ int red[8];
    for (int off = 16; off > 0; off >>= 1) acc += __shfl_xor_sync(0xffffffffu, acc, off);
    if ((tid & 31) == 0) red[tid >> 5] = acc;
    __syncthreads();
    if (tid < 8) {
        int v = red[tid];
        for (int off = 4; off > 0; off >>= 1) v += __shfl_xor_sync(0xffu, v, off);
        if (tid == 0) sums[row] = v;
    }
}

// ---------------- fp16 GEMM + fused Hamming epilogue ----------------
// 256 threads = 8 warps arranged 2 (M) x 4 (N); warp tile 64x32.
// f16 accumulators, spilled exactly to f32 every SPILL_EVERY k-iterations.
__global__ void __launch_bounds__(256, 1) hd_gemm_kernel(float* __restrict__ out) {
    extern __shared__ char smem[];
    const uint32_t smem_base = smem_to_u32(smem);
    const int tid = threadIdx.x;
    const int wid = tid >> 5;
    const int lane = tid & 31;
    const int wm = wid & 1;     // 0..1
    const int wn = wid >> 1;    // 0..3
    const int colTile = blockIdx.x;   // 0..7
    const int rowTile = blockIdx.y;   // 0..63

    const uint16_t* aG = g_A + (size_t)rowTile * BM * D_PAD;
    const uint16_t* bG = g_B + (size_t)colTile * BN * D_PAD;

    // loader mapping: 256 threads x 4 iters x 16B per tile
    const int lr = tid >> 3;   // base row 0..31 (stride 32)
    const int lc = tid & 7;    // 16B chunk 0..7 within 128B row

    auto load_stage = [&](int kt, int s) {
        const uint32_t stBase = smem_base + s * STAGE_BYTES;
        const size_t gchunk = (size_t)kt * 8 + lc;   // 16B chunks; row = 1280 chunks
#pragma unroll
        for (int i = 0; i < 4; ++i) {
            const int r = lr + 32 * i;
            const uint32_t off = (uint32_t)(r * 128 + ((lc ^ (r & 7)) << 4));
            cp_async16(stBase + off,
                       reinterpret_cast<const char*>(aG) + ((size_t)r * 1280 + gchunk) * 16);
            cp_async16(stBase + A_BYTES + off,
                       reinterpret_cast<const char*>(bG) + ((size_t)r * 1280 + gchunk) * 16);
        }
    };

    // ldmatrix lane addressing (as validated in R3)
    const int aLane16 = lane & 15;
    const int aTop = lane >> 4;
    uint32_t aRowOff[4]; int aXor[4];
#pragma unroll
    for (int mt = 0; mt < 4; ++mt) {
        const int r = wm * 64 + mt * 16 + aLane16;
        aRowOff[mt] = (uint32_t)(r * 128);
        aXor[mt] = r & 7;
    }
    const int bRowInTile = ((lane & 16) >> 1) + (lane & 7);
    const int bTop = (lane >> 3) & 1;
    uint32_t bRowOff[2]; int bXor[2];
#pragma unroll
    for (int p = 0; p < 2; ++p) {
        const int r = wn * 32 + p * 16 + bRowInTile;
        bRowOff[p] = (uint32_t)(r * 128);
        bXor[p] = r & 7;
    }

    float facc[4][4][4];        // master fp32 accumulators
    uint32_t hacc[4][4][2];     // working fp16 accumulators (half2 x2)
#pragma unroll
    for (int mt = 0; mt < 4; ++mt)
#pragma unroll
        for (int nt = 0; nt < 4; ++nt) {
#pragma unroll
            for (int q = 0; q < 4; ++q) facc[mt][nt][q] = 0.0f;
            hacc[mt][nt][0] = 0u; hacc[mt][nt][1] = 0u;
        }

    // prologue: 2 stages in flight
    load_stage(0, 0); CP_COMMIT();
    load_stage(1, 1); CP_COMMIT();

    for (int kt = 0; kt < KT; ++kt) {
        CP_WAIT1();
        __syncthreads();
        if (kt + 2 < KT) load_stage(kt + 2, (kt + 2) % STAGES);
        CP_COMMIT();

        const uint32_t aBase = smem_base + (kt % STAGES) * STAGE_BYTES;
        const uint32_t bBase = aBase + A_BYTES;
#pragma unroll
        for (int ks = 0; ks < 4; ++ks) {     // 4 x k16 within BK=64
            uint32_t af[4][4];
#pragma unroll
            for (int mt = 0; mt < 4; ++mt) {
                const int chunk = ks * 2 + aTop;
                const uint32_t addr = aBase + aRowOff[mt] + (uint32_t)((chunk ^ aXor[mt]) << 4);
                LDSM_X4(af[mt][0], af[mt][1], af[mt][2], af[mt][3], addr);
            }
            uint32_t bf[4][2];
#pragma unroll
            for (int p = 0; p < 2; ++p) {
                const int chunk = ks * 2 + bTop;
                const uint32_t addr = bBase + bRowOff[p] + (uint32_t)((chunk ^ bXor[p]) << 4);
                LDSM_X4(bf[2 * p][0], bf[2 * p][1], bf[2 * p + 1][0], bf[2 * p + 1][1], addr);
            }
#pragma unroll
            for (int mt = 0; mt < 4; ++mt)
#pragma unroll
                for (int nt = 0; nt < 4; ++nt)
                    MMA_F16ACC(hacc[mt][nt], af[mt], bf[nt]);
        }

        // exact spill: partial f16 sums <= 2048 are integers, exactly representable
        if ((kt & (SPILL_EVERY - 1)) == (SPILL_EVERY - 1)) {
#pragma unroll
            for (int mt = 0; mt < 4; ++mt)
#pragma unroll
                for (int nt = 0; nt < 4; ++nt) {
                    float2 lo = __half22float2(*reinterpret_cast<__half2*>(&hacc[mt][nt][0]));
                    float2 hi = __half22float2(*reinterpret_cast<__half2*>(&hacc[mt][nt][1]));
                    facc[mt][nt][0] += lo.x;
                    facc[mt][nt][1] += lo.y;
                    facc[mt][nt][2] += hi.x;
                    facc[mt][nt][3] += hi.y;
                    hacc[mt][nt][0] = 0u; hacc[mt][nt][1] = 0u;
                }
        }
    }

    // ---------------- epilogue: dist = ssum + csum - 2*dot (exact) ----
    const int groupID = lane >> 2;   // 0..7
    const int tig = lane & 3;        // 0..3
#pragma unroll
    for (int mt = 0; mt < 4; ++mt) {
        const int m0 = rowTile * BM + wm * 64 + mt * 16 + groupID;
        const float s0 = (float)g_ssum[m0];
        const float s1 = (float)g_ssum[m0 + 8];
        float* orow0 = out + (size_t)m0 * C_CLS;
        float* orow1 = out + (size_t)(m0 + 8) * C_CLS;
#pragma unroll
        for (int nt = 0; nt < 4; ++nt) {
            const int c0 = colTile * BN + wn * 32 + nt * 8 + 2 * tig;
            if (c0 < C_CLS) {   // C_CLS even; pair fully valid
                const float cs0 = (float)g_csum[c0];
                const float cs1 = (float)g_csum[c0 + 1];
                float2 v0, v1;
                v0.x = s0 + cs0 - 2.0f * facc[mt][nt][0];
                v0.y = s0 + cs1 - 2.0f * facc[mt][nt][1];
                v1.x = s1 + cs0 - 2.0f * facc[mt][nt][2];
                v1.y = s1 + cs1 - 2.0f * facc[mt][nt][3];
                *reinterpret_cast<float2*>(orow0 + c0) = v0;
                *reinterpret_cast<float2*>(orow1 + c0) = v1;
            }
        }
    }
}

// ---------------- launch ----------------
extern "C" void kernel_launch(void* const* d_in, const int* in_sizes, int n_in,
                              void* d_out, int out_size) {
    const float* samples = (const float*)d_in[0];   // [8192, 10000]
    const float* classes = (const float*)d_in[1];   // [1000, 10000]
    float* out = (float*)d_out;                     // [8192, 1000]

    uint16_t* gA; cudaGetSymbolAddress((void**)&gA, g_A);
    uint16_t* gB; cudaGetSymbolAddress((void**)&gB, g_B);
    int* gs; cudaGetSymbolAddress((void**)&gs, g_ssum);
    int* gc; cudaGetSymbolAddress((void**)&gc, g_csum);

    cudaFuncSetAttribute(hd_gemm_kernel, cudaFuncAttributeMaxDynamicSharedMemorySize,
                         SMEM_TOTAL);

    cvt_kernel<<<N_ROWS, 256>>>(samples, gA, gs, N_ROWS);
    cvt_kernel<<<C_PAD, 256>>>(classes, gB, gc, C_CLS);

    dim3 grid(C_PAD / BN, N_ROWS / BM);  // (8, 64)
    hd_gemm_kernel<<<grid, 256, SMEM_TOTAL>>>(out);
}

// round 7
// speedup vs baseline: 1.2372x; 1.2372x over previous
#include <cuda_runtime.h>
#include <cstdint>

// ---------------- problem dims ----------------
static constexpr int N_ROWS = 8192;    // samples
static constexpr int C_CLS  = 1000;    // classes
static constexpr int D_DIM  = 10000;   // hypervector dim
static constexpr int D_PAD  = 10240;   // padded: 160 * 64 (zeros contribute 0 to dot)
static constexpr int C_PAD  = 1024;    // padded classes (rows >= 1000 are zero)

// ---------------- GEMM tiling (bf16) ----------------
static constexpr int BM = 64;
static constexpr int BN = 128;
static constexpr int BK = 64;               // 64 bf16 = 128B rows
static constexpr int KT = D_PAD / BK;       // 160 K-iterations
static constexpr int STAGES = 3;

static constexpr int A_BYTES = BM * BK * 2;            // 8192
static constexpr int STAGE_BYTES = (BM + BN) * BK * 2; // 24576
static constexpr int SMEM_TOTAL = STAGES * STAGE_BYTES; // 73728 -> 3 CTAs/SM

// ---------------- scratch (device globals; no allocation allowed) ----------
__device__ uint16_t g_A[(size_t)N_ROWS * D_PAD];   // 168 MB bf16
__device__ uint16_t g_B[(size_t)C_PAD  * D_PAD];   // 21 MB bf16
__device__ int g_ssum[N_ROWS];
__device__ int g_csum[C_PAD];

// ---------------- helpers ----------------
__device__ __forceinline__ uint32_t smem_to_u32(const void* p) {
    uint32_t a;
    asm("{ .reg .u64 t; cvta.to.shared.u64 t, %1; cvt.u32.u64 %0, t; }" : "=r"(a) : "l"(p));
    return a;
}

__device__ __forceinline__ void cp_async16(uint32_t smem_addr, const void* gptr) {
    asm volatile("cp.async.cg.shared.global [%0], [%1], 16;"
                 :: "r"(smem_addr), "l"(gptr) : "memory");
}
#define CP_COMMIT() asm volatile("cp.async.commit_group;" ::: "memory")
#define CP_WAIT1()  asm volatile("cp.async.wait_group 1;" ::: "memory")

#define LDSM_X4(r0, r1, r2, r3, addr) \
    asm volatile("ldmatrix.sync.aligned.m8n8.x4.shared.b16 {%0,%1,%2,%3}, [%4];" \
                 : "=r"(r0), "=r"(r1), "=r"(r2), "=r"(r3) : "r"(addr))

// bf16 MMA, fp32 accumulate: D += A(16x16) * B(16x8)^T
#define MMA_BF16(d, a, b) \
    asm volatile("mma.sync.aligned.m16n8k16.row.col.f32.bf16.bf16.f32 " \
                 "{%0,%1,%2,%3}, {%4,%5,%6,%7}, {%8,%9}, {%0,%1,%2,%3};" \
                 : "+f"((d)[0]), "+f"((d)[1]), "+f"((d)[2]), "+f"((d)[3]) \
                 : "r"((a)[0]), "r"((a)[1]), "r"((a)[2]), "r"((a)[3]), \
                   "r"((b)[0]), "r"((b)[1]))

// pack two {0,1} floats into one u32 holding two bf16 (exact truncation)
__device__ __forceinline__ uint32_t packbf2(float lo, float hi) {
    return __byte_perm(__float_as_uint(lo), __float_as_uint(hi), 0x7632);
}

// ---------------- conversion: fp32 {0,1} -> bf16, fused integer row-sum ----
__global__ void __launch_bounds__(256) cvt_kernel(const float* __restrict__ src,
                                                  uint16_t* __restrict__ dst,
                                                  int* __restrict__ sums,
                                                  int valid_rows) {
    const int row = blockIdx.x;
    const int tid = threadIdx.x;
    int acc = 0;
    uint4* d4 = reinterpret_cast<uint4*>(dst + (size_t)row * D_PAD);  // 16B = 8 bf16
    if (row < valid_rows) {
        const float4* s4 = reinterpret_cast<const float4*>(src + (size_t)row * D_DIM);
        // D_DIM/8 = 1250 full 8-elem chunks; chunks 1250..1279 are zero padding
        for (int i = tid; i < D_PAD / 8; i += 256) {
            uint4 o;
            if (i < D_DIM / 8) {
                float4 v0 = s4[i * 2 + 0];
                float4 v1 = s4[i * 2 + 1];
                float fs = v0.x + v0.y + v0.z + v0.w + v1.x + v1.y + v1.z + v1.w;
                acc += (int)fs;   // sum of 8 {0,1} values: exact
                o.x = packbf2(v0.x, v0.y);
                o.y = packbf2(v0.z, v0.w);
                o.z = packbf2(v1.x, v1.y);
                o.w = packbf2(v1.z, v1.w);
            } else {
                o.x = 0u; o.y = 0u; o.z = 0u; o.w = 0u;
            }
            d4[i] = o;
        }
    } else {
        uint4 z; z.x = 0u; z.y = 0u; z.z = 0u; z.w = 0u;
        for (int i = tid; i < D_PAD / 8; i += 256) d4[i] = z;
    }
    // block reduce (int)
    __shared__ int red[8];
    for (int off = 16; off > 0; off >>= 1) acc += __shfl_xor_sync(0xffffffffu, acc, off);
    if ((tid & 31) == 0) red[tid >> 5] = acc;
    __syncthreads();
    if (tid < 8) {
        int v = red[tid];
        for (int off = 4; off > 0; off >>= 1) v += __shfl_xor_sync(0xffu, v, off);
        if (tid == 0) sums[row] = v;
    }
}

// ---------------- bf16 GEMM + fused Hamming epilogue ----------------
// Block tile 64x128, 256 threads = 8 warps arranged 2 (M) x 4 (N);
// warp tile 32x32. 1024 tiles -> 6.92 tiles/SM (tail ~1%), 3 CTAs/SM.
// Smem rows = 128B with 16B-chunk swizzle: chunk ^= row&7.
__global__ void __launch_bounds__(256, 3) hd_gemm_kernel(float* __restrict__ out) {
    extern __shared__ char smem[];
    const uint32_t smem_base = smem_to_u32(smem);
    const int tid = threadIdx.x;
    const int wid = tid >> 5;
    const int lane = tid & 31;
    const int wm = wid & 1;     // 0..1  (M)
    const int wn = wid >> 1;    // 0..3  (N)
    const int colTile = blockIdx.x;   // 0..7
    const int rowTile = blockIdx.y;   // 0..127

    const uint16_t* aG = g_A + (size_t)rowTile * BM * D_PAD;
    const uint16_t* bG = g_B + (size_t)colTile * BN * D_PAD;

    // loader mapping: combined 192 rows (A rows 0..63, B rows 64..191),
    // 256 threads x 6 iters x 16B. dst region is contiguous: A then B.
    const int lr = tid >> 3;   // base row 0..31 (stride 32)
    const int lc = tid & 7;    // 16B chunk 0..7 within 128B row

    auto load_stage = [&](int kt, int s) {
        const uint32_t stBase = smem_base + s * STAGE_BYTES;
        const size_t gchunk = (size_t)kt * 8 + lc;   // 16B chunks; row = 1280 chunks
#pragma unroll
        for (int i = 0; i < 6; ++i) {
            const int r = lr + 32 * i;               // 0..191
            const uint32_t off = (uint32_t)(r * 128 + ((lc ^ (r & 7)) << 4));
            const char* src = (i < 2)
                ? reinterpret_cast<const char*>(aG) + ((size_t)r * 1280 + gchunk) * 16
                : reinterpret_cast<const char*>(bG) + ((size_t)(r - 64) * 1280 + gchunk) * 16;
            cp_async16(stBase + off, src);
        }
    };

    // ldmatrix lane addressing (validated R3 scheme)
    const int aLane16 = lane & 15;
    const int aTop = lane >> 4;              // chunk offset 0/1 within the 32B k16
    uint32_t aRowOff[2]; int aXor[2];
#pragma unroll
    for (int mt = 0; mt < 2; ++mt) {
        const int r = wm * 32 + mt * 16 + aLane16;      // A rows 0..63
        aRowOff[mt] = (uint32_t)(r * 128);
        aXor[mt] = r & 7;
    }
    const int bRowInTile = ((lane & 16) >> 1) + (lane & 7);  // +8 for lanes>=16
    const int bTop = (lane >> 3) & 1;        // chunk offset 0/1
    uint32_t bRowOff[2]; int bXor[2];
#pragma unroll
    for (int p = 0; p < 2; ++p) {
        const int r = wn * 32 + p * 16 + bRowInTile;    // B rows 0..127
        bRowOff[p] = (uint32_t)(r * 128);
        bXor[p] = r & 7;
    }

    float acc[2][4][4];
#pragma unroll
    for (int mt = 0; mt < 2; ++mt)
#pragma unroll
        for (int nt = 0; nt < 4; ++nt)
#pragma unroll
            for (int q = 0; q < 4; ++q) acc[mt][nt][q] = 0.0f;

    // prologue: 2 stages in flight
    load_stage(0, 0); CP_COMMIT();
    load_stage(1, 1); CP_COMMIT();

    for (int kt = 0; kt < KT; ++kt) {
        CP_WAIT1();
        __syncthreads();
        if (kt + 2 < KT) load_stage(kt + 2, (kt + 2) % STAGES);
        CP_COMMIT();

        const uint32_t aBase = smem_base + (kt % STAGES) * STAGE_BYTES;
        const uint32_t bBase = aBase + A_BYTES;
#pragma unroll
        for (int ks = 0; ks < 4; ++ks) {     // 4 x k16 within BK=64
            uint32_t af[2][4];
#pragma unroll
            for (int mt = 0; mt < 2; ++mt) {
                const int chunk = ks * 2 + aTop;
                const uint32_t addr = aBase + aRowOff[mt] + (uint32_t)((chunk ^ aXor[mt]) << 4);
                LDSM_X4(af[mt][0], af[mt][1], af[mt][2], af[mt][3], addr);
            }
            uint32_t bf[4][2];
#pragma unroll
            for (int p = 0; p < 2; ++p) {
                const int chunk = ks * 2 + bTop;
                const uint32_t addr = bBase + bRowOff[p] + (uint32_t)((chunk ^ bXor[p]) << 4);
                LDSM_X4(bf[2 * p][0], bf[2 * p][1], bf[2 * p + 1][0], bf[2 * p + 1][1], addr);
            }
#pragma unroll
            for (int mt = 0; mt < 2; ++mt)
#pragma unroll
                for (int nt = 0; nt < 4; ++nt)
                    MMA_BF16(acc[mt][nt], af[mt], bf[nt]);
        }
    }

    // ---------------- epilogue: dist = ssum + csum - 2*dot (exact) ----
    const int groupID = lane >> 2;   // 0..7
    const int tig = lane & 3;        // 0..3
#pragma unroll
    for (int mt = 0; mt < 2; ++mt) {
        const int m0 = rowTile * BM + wm * 32 + mt * 16 + groupID;
        const float s0 = (float)g_ssum[m0];
        const float s1 = (float)g_ssum[m0 + 8];
        float* orow0 = out + (size_t)m0 * C_CLS;
        float* orow1 = out + (size_t)(m0 + 8) * C_CLS;
#pragma unroll
        for (int nt = 0; nt < 4; ++nt) {
            const int c0 = colTile * BN + wn * 32 + nt * 8 + 2 * tig;
            if (c0 < C_CLS) {   // C_CLS even; pair fully valid
                const float cs0 = (float)g_csum[c0];
                const float cs1 = (float)g_csum[c0 + 1];
                float2 v0, v1;
                v0.x = s0 + cs0 - 2.0f * acc[mt][nt][0];
                v0.y = s0 + cs1 - 2.0f * acc[mt][nt][1];
                v1.x = s1 + cs0 - 2.0f * acc[mt][nt][2];
                v1.y = s1 + cs1 - 2.0f * acc[mt][nt][3];
                *reinterpret_cast<float2*>(orow0 + c0) = v0;
                *reinterpret_cast<float2*>(orow1 + c0) = v1;
            }
        }
    }
}

// ---------------- launch ----------------
extern "C" void kernel_launch(void* const* d_in, const int* in_sizes, int n_in,
                              void* d_out, int out_size) {
    const float* samples = (const float*)d_in[0];   // [8192, 10000]
    const float* classes = (const float*)d_in[1];   // [1000, 10000]
    float* out = (float*)d_out;                     // [8192, 1000]

    uint16_t* gA; cudaGetSymbolAddress((void**)&gA, g_A);
    uint16_t* gB; cudaGetSymbolAddress((void**)&gB, g_B);
    int* gs; cudaGetSymbolAddress((void**)&gs, g_ssum);
    int* gc; cudaGetSymbolAddress((void**)&gc, g_csum);

    cudaFuncSetAttribute(hd_gemm_kernel, cudaFuncAttributeMaxDynamicSharedMemorySize,
                         SMEM_TOTAL);

    cvt_kernel<<<N_ROWS, 256>>>(samples, gA, gs, N_ROWS);
    cvt_kernel<<<C_PAD, 256>>>(classes, gB, gc, C_CLS);

    dim3 grid(C_PAD / BN, N_ROWS / BM);  // (8, 128) = 1024 tiles
    hd_gemm_kernel<<<grid, 256, SMEM_TOTAL>>>(out);
}